// round 10
// baseline (speedup 1.0000x reference)
#include <cuda_runtime.h>
#include <cuda_bf16.h>
#include <math.h>

#define BB 32
#define PP 64
#define LL 64
#define VV 32000
#define NROWS (BB * PP)            // 2048 rows
#define CH    4                    // chunks per row
#define CHUNK (VV / 4 / CH)        // 2000 float4 per chunk
#define NBLK  (BB + NROWS * CH)    // 32 DP blocks + 8192 chunk blocks

// Scratch (__device__ globals — no allocation allowed). Zero-init at load;
// the winner block resets mutable state at the end of every launch.
__device__ int      g_len[BB];
__device__ unsigned g_mask32[NROWS * 2];     // argmin bitmask per (b,i)
__device__ float    g_part[NROWS * CH];      // per-chunk partial sums
__device__ int      g_rowctr[NROWS];         // chunks completed per row
__device__ float    g_loss[NROWS];
__device__ volatile int g_dp_done[BB];
__device__ unsigned g_ctr;

// ---------------------------------------------------------------------------
__device__ __forceinline__ int mask_mode(const void* mask) {
    unsigned w = *(const unsigned*)mask;     // lengths >= 32 -> first 4 true
    if (w == 0x01010101u) return 0;          // 1-byte bool
    if (w == 0x3F800000u) return 2;          // float32
    if (w == 0x3F803F80u) return 3;          // bf16
    return 1;                                // int32
}
__device__ __forceinline__ bool mask_at(const void* mask, int mode, int idx) {
    if (mode == 0) return ((const unsigned char*)mask)[idx] != 0;
    if (mode == 1) return ((const int*)mask)[idx] != 0;
    if (mode == 2) return ((const float*)mask)[idx] != 0.0f;
    return ((const unsigned short*)mask)[idx] != 0;
}

// ---------------------------------------------------------------------------
// Single-warp edit-distance DP for batch b (2 columns per lane, no barriers).
// Row recurrence matches reference: tmp = min(diag + neq, ins + 1);
// cur[j] = j + cummin_{k<=j}(tmp[k] - k). Values are exact small ints in fp32.
// ---------------------------------------------------------------------------
__device__ void dp_warp(int b, const int* __restrict__ syms,
                        const int* __restrict__ targets,
                        const void* __restrict__ mask, int mode) {
    const unsigned FULL = 0xffffffffu;
    const int lane = threadIdx.x;            // 0..31
    const int j0 = lane, j1 = lane + 32;

    int t0 = targets[b * LL + j0];
    int t1 = targets[b * LL + j1];
    int tp0 = __shfl_up_sync(FULL, t0, 1);   // targ[j0-1] (lane>0)
    int tp1 = __shfl_up_sync(FULL, t1, 1);
    int t0_31 = __shfl_sync(FULL, t0, 31);
    if (lane == 0) tp1 = t0_31;              // targ[31]

    int s0 = syms[b * PP + j0];
    int s1 = syms[b * PP + j1];

    bool m0 = mask_at(mask, mode, b * LL + j0);
    bool m1 = mask_at(mask, mode, b * LL + j1);
    int len = __popc(__ballot_sync(FULL, m0)) + __popc(__ballot_sync(FULL, m1));
    if (lane == 0) g_len[b] = len;

    float prev0 = (float)j0, prev1 = (float)j1;   // row 0
    if (lane == 0) {                              // row 0 argmin: j=0 only
        g_mask32[(b * PP) * 2 + 0] = 1u;
        g_mask32[(b * PP) * 2 + 1] = 0u;
    }

    for (int i = 1; i < PP; i++) {
        int sa = __shfl_sync(FULL, s0, (i - 1) & 31);
        int sb = __shfl_sync(FULL, s1, (i - 1) & 31);
        int sym = (i <= 32) ? sa : sb;

        float d0 = __shfl_up_sync(FULL, prev0, 1);   // prev[j0-1]
        float d1 = __shfl_up_sync(FULL, prev1, 1);
        float p31 = __shfl_sync(FULL, prev0, 31);
        if (lane == 0) d1 = p31;

        float n0 = (sym != tp0) ? 1.0f : 0.0f;
        float n1 = (sym != tp1) ? 1.0f : 0.0f;
        float tmp0 = fminf(d0 + n0, prev0 + 1.0f);
        if (lane == 0) tmp0 = (float)i;
        float tmp1 = fminf(d1 + n1, prev1 + 1.0f);

        float sc0 = tmp0 - (float)j0;
        float sc1 = tmp1 - (float)j1;
        #pragma unroll
        for (int off = 1; off < 32; off <<= 1) {     // interleaved min-scans
            float a0 = __shfl_up_sync(FULL, sc0, off);
            float a1 = __shfl_up_sync(FULL, sc1, off);
            if (lane >= off) { sc0 = fminf(sc0, a0); sc1 = fminf(sc1, a1); }
        }
        float tot0 = __shfl_sync(FULL, sc0, 31);
        sc1 = fminf(sc1, tot0);
        float cur0 = sc0 + (float)j0;
        float cur1 = sc1 + (float)j1;

        float v0 = (j0 < len) ? cur0 : 3.0e38f;
        float v1 = (j1 < len) ? cur1 : 3.0e38f;
        float r = fminf(v0, v1);
        #pragma unroll
        for (int off = 16; off; off >>= 1)
            r = fminf(r, __shfl_xor_sync(FULL, r, off));

        unsigned b0 = __ballot_sync(FULL, v0 == r);
        unsigned b1 = __ballot_sync(FULL, v1 == r);
        if (lane == 0) {
            g_mask32[(b * PP + i) * 2 + 0] = b0;
            g_mask32[(b * PP + i) * 2 + 1] = b1;
        }
        prev0 = cur0; prev1 = cur1;
    }
    __threadfence();
    if (lane == 0) g_dp_done[b] = 1;
}

// ---------------------------------------------------------------------------
// One fused kernel:
//   blocks 0..31                  : DP per batch (wave-1 resident, ~5us)
//   blocks 32..32+8191            : one 32KB chunk of one row each; the chunk
//                                   that completes a row (per-row counter)
//                                   finalizes that row's loss deterministically
//   last block to finish (ticket) : final scalar + state reset for replay
// ---------------------------------------------------------------------------
__global__ void __launch_bounds__(256)
fused_kernel(const float* __restrict__ outputs,
             const int* __restrict__ syms,
             const int* __restrict__ targets,
             const void* __restrict__ mask,
             float* __restrict__ out) {
    const int tid = threadIdx.x;
    const int mode = mask_mode(mask);
    __shared__ int   targ[LL];
    __shared__ float sw[8];
    __shared__ float sh_hv[2];
    __shared__ int   sh_fl[2];
    __shared__ int   sh_old;
    __shared__ int   sh_win;
    __shared__ float pb[BB];

    if (blockIdx.x < BB) {
        // ---------------- DP role ----------------
        if (tid < 32) dp_warp(blockIdx.x, syms, targets, mask, mode);
    } else {
        // ---------------- chunk role ----------------
        const int id  = blockIdx.x - BB;         // 0..8191
        const int blk = id >> 2;                 // row 0..2047
        const int c   = id & (CH - 1);           // chunk 0..3
        const int b = blk >> 6, i = blk & 63;

        // own-row mask length (no dependency on DP blocks)
        bool mb = (tid < LL) && mask_at(mask, mode, b * LL + tid);
        int len = __syncthreads_count(mb);

        if (i >= len) {
            if (c == 0 && tid == 0) g_loss[blk] = 0.0f;
        } else {
            const float* row = outputs + (size_t)blk * VV;
            const float4* r4 = (const float4*)row + c * CHUNK;   // 2000 float4

            float acc = 0.0f;
            #pragma unroll 4
            for (int idx = tid; idx < CHUNK; idx += 256) {
                float4 v = __ldcs(r4 + idx);
                acc += (v.x + v.y) + (v.z + v.w);
            }
            #pragma unroll
            for (int off = 16; off; off >>= 1)
                acc += __shfl_xor_sync(0xffffffffu, acc, off);
            if ((tid & 31) == 0) sw[tid >> 5] = acc;
            __syncthreads();

            if (tid == 0) {
                float part = 0.0f;
                for (int k = 0; k < 8; k++) part += sw[k];
                g_part[id] = part;
                __threadfence();                       // release partial
                sh_old = atomicAdd(&g_rowctr[blk], 1); // completion ticket
            }
            __syncthreads();

            if (sh_old == CH - 1) {
                // -------- row finalizer (deterministic) --------
                __threadfence();                       // acquire partials
                if (tid < LL) targ[tid] = targets[b * LL + tid];
                if (tid == 0) { while (g_dp_done[b] == 0) { } }
                __syncthreads();
                __threadfence();

                if (tid < 64) {      // hit-set dedup + gather
                    unsigned lo = g_mask32[blk * 2 + 0];
                    unsigned hi = g_mask32[blk * 2 + 1];
                    int j = tid;
                    bool hit = (j < 32) ? ((lo >> j) & 1u) : ((hi >> (j - 32)) & 1u);
                    float val = 0.0f; int flag = 0;
                    if (hit) {
                        int cc = targ[j];
                        bool first = true;
                        for (int k = 0; k < j; k++) {
                            bool hk = (k < 32) ? ((lo >> k) & 1u)
                                               : ((hi >> (k - 32)) & 1u);
                            if (hk && targ[k] == cc) { first = false; break; }
                        }
                        if (first) { val = row[cc]; flag = 1; }
                    }
                    #pragma unroll
                    for (int off = 16; off; off >>= 1) {
                        val  += __shfl_xor_sync(0xffffffffu, val, off);
                        flag += __shfl_xor_sync(0xffffffffu, flag, off);
                    }
                    if ((tid & 31) == 0) { sh_hv[tid >> 5] = val; sh_fl[tid >> 5] = flag; }
                }
                __syncthreads();

                if (tid == 0) {
                    float S_all = 0.0f;                // fixed-order combine
                    #pragma unroll
                    for (int k = 0; k < CH; k++) S_all += g_part[blk * CH + k];
                    float S_hit = sh_hv[0] + sh_hv[1];
                    int   m     = sh_fl[0] + sh_fl[1];

                    const float em1 = 0.36787944117144233f;  // e^-1
                    float fm = (float)m;
                    float Z  = fm + ((float)VV - fm) * em1;
                    float ph = 1.0f / Z;
                    float pm = em1 / Z;
                    float ent = fm * ph * logf(ph) + ((float)VV - fm) * pm * logf(pm);
                    g_loss[blk] = ent - (pm * S_all + (ph - pm) * S_hit);
                }
            }
        }
    }

    // ---------------- ticket: last block does the final scalar ----------------
    __syncthreads();
    if (tid == 0) {
        __threadfence();                          // release my g_* writes
        unsigned old = atomicAdd(&g_ctr, 1u);
        sh_win = (old == NBLK - 1) ? 1 : 0;
    }
    __syncthreads();

    if (sh_win) {
        __threadfence();                          // acquire everyone's writes
        if (tid < BB) {
            float s = 0.0f;
            for (int i = 0; i < PP; i++) s += g_loss[tid * PP + i];
            pb[tid] = s / ((float)g_len[tid] + 1e-13f);
        }
        __syncthreads();
        if (tid == 0) {
            float acc = 0.0f, n = 0.0f;
            for (int k = 0; k < BB; k++) {
                acc += pb[k];
                if (g_len[k] > 0) n += 1.0f;
            }
            out[0] = acc / (n + 1e-13f);
            g_ctr = 0;
            for (int k = 0; k < BB; k++) g_dp_done[k] = 0;
        }
        // reset per-row counters for the next graph replay
        for (int k = tid; k < NROWS; k += 256) g_rowctr[k] = 0;
    }
}

// ---------------------------------------------------------------------------
extern "C" void kernel_launch(void* const* d_in, const int* in_sizes, int n_in,
                              void* d_out, int out_size) {
    const float* outputs = (const float*)d_in[0];   // (B,P,V) f32 log-probs
    const int*   syms    = (const int*)d_in[1];     // (B,P) i32
    const int*   targets = (const int*)d_in[2];     // (B,L) i32
    const void*  mask    = d_in[3];                 // (B,L) bool-ish

    fused_kernel<<<NBLK, 256>>>(outputs, syms, targets, mask, (float*)d_out);
}

// round 12
// speedup vs baseline: 1.1231x; 1.1231x over previous
#include <cuda_runtime.h>
#include <cuda_bf16.h>
#include <math.h>

#define BB 32
#define PP 64
#define LL 64
#define VV 32000
#define NROWS (BB * PP)            // 2048 rows
#define NWORK 1152                 // persistent worker blocks
#define NBLK  (BB + NWORK)         // + 32 DP blocks = 1184 (~one wave)

// Scratch (__device__ globals — no allocation allowed). Zero-init at load;
// the winner block resets mutable state at the end of every launch.
__device__ int      g_len[BB];
__device__ unsigned g_mask32[NROWS * 2];     // argmin bitmask per (b,i)
__device__ float    g_loss[NROWS];
__device__ volatile int g_dp_done[BB];
__device__ unsigned g_work;                  // row work queue
__device__ unsigned g_ctr;                   // exit ticket

// ---------------------------------------------------------------------------
__device__ __forceinline__ int mask_mode(const void* mask) {
    unsigned w = *(const unsigned*)mask;     // lengths >= 32 -> first 4 true
    if (w == 0x01010101u) return 0;          // 1-byte bool
    if (w == 0x3F800000u) return 2;          // float32
    if (w == 0x3F803F80u) return 3;          // bf16
    return 1;                                // int32
}
__device__ __forceinline__ bool mask_at(const void* mask, int mode, int idx) {
    if (mode == 0) return ((const unsigned char*)mask)[idx] != 0;
    if (mode == 1) return ((const int*)mask)[idx] != 0;
    if (mode == 2) return ((const float*)mask)[idx] != 0.0f;
    return ((const unsigned short*)mask)[idx] != 0;
}

// ---------------------------------------------------------------------------
// Single-warp edit-distance DP for batch b (2 columns per lane, no barriers).
// Row recurrence matches reference: tmp = min(diag + neq, ins + 1);
// cur[j] = j + cummin_{k<=j}(tmp[k] - k). Values are exact small ints in fp32.
// ---------------------------------------------------------------------------
__device__ void dp_warp(int b, const int* __restrict__ syms,
                        const int* __restrict__ targets,
                        const void* __restrict__ mask, int mode) {
    const unsigned FULL = 0xffffffffu;
    const int lane = threadIdx.x;            // 0..31
    const int j0 = lane, j1 = lane + 32;

    int t0 = targets[b * LL + j0];
    int t1 = targets[b * LL + j1];
    int tp0 = __shfl_up_sync(FULL, t0, 1);   // targ[j0-1] (lane>0)
    int tp1 = __shfl_up_sync(FULL, t1, 1);
    int t0_31 = __shfl_sync(FULL, t0, 31);
    if (lane == 0) tp1 = t0_31;              // targ[31]

    int s0 = syms[b * PP + j0];
    int s1 = syms[b * PP + j1];

    bool m0 = mask_at(mask, mode, b * LL + j0);
    bool m1 = mask_at(mask, mode, b * LL + j1);
    int len = __popc(__ballot_sync(FULL, m0)) + __popc(__ballot_sync(FULL, m1));
    if (lane == 0) g_len[b] = len;

    float prev0 = (float)j0, prev1 = (float)j1;   // row 0
    if (lane == 0) {                              // row 0 argmin: j=0 only
        g_mask32[(b * PP) * 2 + 0] = 1u;
        g_mask32[(b * PP) * 2 + 1] = 0u;
    }

    for (int i = 1; i < PP; i++) {
        int sa = __shfl_sync(FULL, s0, (i - 1) & 31);
        int sb = __shfl_sync(FULL, s1, (i - 1) & 31);
        int sym = (i <= 32) ? sa : sb;

        float d0 = __shfl_up_sync(FULL, prev0, 1);   // prev[j0-1]
        float d1 = __shfl_up_sync(FULL, prev1, 1);
        float p31 = __shfl_sync(FULL, prev0, 31);
        if (lane == 0) d1 = p31;

        float n0 = (sym != tp0) ? 1.0f : 0.0f;
        float n1 = (sym != tp1) ? 1.0f : 0.0f;
        float tmp0 = fminf(d0 + n0, prev0 + 1.0f);
        if (lane == 0) tmp0 = (float)i;
        float tmp1 = fminf(d1 + n1, prev1 + 1.0f);

        float sc0 = tmp0 - (float)j0;
        float sc1 = tmp1 - (float)j1;
        #pragma unroll
        for (int off = 1; off < 32; off <<= 1) {     // interleaved min-scans
            float a0 = __shfl_up_sync(FULL, sc0, off);
            float a1 = __shfl_up_sync(FULL, sc1, off);
            if (lane >= off) { sc0 = fminf(sc0, a0); sc1 = fminf(sc1, a1); }
        }
        float tot0 = __shfl_sync(FULL, sc0, 31);
        sc1 = fminf(sc1, tot0);
        float cur0 = sc0 + (float)j0;
        float cur1 = sc1 + (float)j1;

        float v0 = (j0 < len) ? cur0 : 3.0e38f;
        float v1 = (j1 < len) ? cur1 : 3.0e38f;
        float r = fminf(v0, v1);
        #pragma unroll
        for (int off = 16; off; off >>= 1)
            r = fminf(r, __shfl_xor_sync(FULL, r, off));

        unsigned b0 = __ballot_sync(FULL, v0 == r);
        unsigned b1 = __ballot_sync(FULL, v1 == r);
        if (lane == 0) {
            g_mask32[(b * PP + i) * 2 + 0] = b0;
            g_mask32[(b * PP + i) * 2 + 1] = b1;
        }
        prev0 = cur0; prev1 = cur1;
    }
    __threadfence();
    if (lane == 0) g_dp_done[b] = 1;
}

// ---------------------------------------------------------------------------
// One fused kernel:
//   blocks 0..31   : DP per batch (wave-1 resident, ~5us)
//   blocks 32..    : persistent workers; each decodes all batch lengths once,
//                    then dynamically steals rows from a global queue and
//                    processes whole rows (stream-sum + hit-gather + loss)
//   last block     : (exit ticket) deterministic final scalar + state reset
// ---------------------------------------------------------------------------
__global__ void __launch_bounds__(256)
fused_kernel(const float* __restrict__ outputs,
             const int* __restrict__ syms,
             const int* __restrict__ targets,
             const void* __restrict__ mask,
             float* __restrict__ out) {
    const int tid = threadIdx.x;
    const int mode = mask_mode(mask);
    __shared__ int   s_len[BB];
    __shared__ int   targ[LL];
    __shared__ float sw[8];
    __shared__ float sh_hv[2];
    __shared__ int   sh_fl[2];
    __shared__ int   sh_row;
    __shared__ int   sh_win;
    __shared__ float pb[BB];

    if (blockIdx.x < BB) {
        // ---------------- DP role ----------------
        if (tid < 32) dp_warp(blockIdx.x, syms, targets, mask, mode);
    } else {
        // ---------------- persistent worker role ----------------
        // Decode all 32 batch lengths once: thread t counts 8 mask entries.
        if (tid < BB) s_len[tid] = 0;
        __syncthreads();
        {
            int b = tid >> 3, sub = tid & 7;       // 256 threads -> 32x8
            int cnt = 0;
            #pragma unroll
            for (int k = 0; k < 8; k++)
                cnt += mask_at(mask, mode, b * LL + sub * 8 + k) ? 1 : 0;
            atomicAdd(&s_len[b], cnt);
        }
        __syncthreads();

        for (;;) {
            if (tid == 0) sh_row = (int)atomicAdd(&g_work, 1u);
            __syncthreads();
            const int row = sh_row;
            if (row >= NROWS) break;
            const int b = row >> 6, i = row & 63;

            if (i >= s_len[b]) {
                if (tid == 0) g_loss[row] = 0.0f;
                __syncthreads();                   // keep block converged
                continue;
            }

            const float* rowp = outputs + (size_t)row * VV;
            const float4* r4 = (const float4*)rowp;    // 8000 float4
            if (tid < LL) targ[tid] = targets[b * LL + tid];

            // streaming row sum: constant 31-trip loop (8000 = 31*256 + 64)
            float acc = 0.0f;
            #pragma unroll 4
            for (int k = 0; k < 31; k++) {
                float4 v = __ldcs(r4 + tid + (k << 8));
                acc += (v.x + v.y) + (v.z + v.w);
            }
            if (tid < 64) {
                float4 v = __ldcs(r4 + 7936 + tid);
                acc += (v.x + v.y) + (v.z + v.w);
            }
            #pragma unroll
            for (int off = 16; off; off >>= 1)
                acc += __shfl_xor_sync(0xffffffffu, acc, off);
            if ((tid & 31) == 0) sw[tid >> 5] = acc;

            // DP for this batch finished long ago (wave-1, ~5us vs ~30us)
            if (tid == 0) { while (g_dp_done[b] == 0) { } }
            __syncthreads();
            __threadfence();

            if (tid < 64) {        // hit-set dedup + gather
                unsigned lo = g_mask32[row * 2 + 0];
                unsigned hi = g_mask32[row * 2 + 1];
                int j = tid;
                bool hit = (j < 32) ? ((lo >> j) & 1u) : ((hi >> (j - 32)) & 1u);
                float val = 0.0f; int flag = 0;
                if (hit) {
                    int cc = targ[j];
                    bool first = true;
                    for (int k = 0; k < j; k++) {
                        bool hk = (k < 32) ? ((lo >> k) & 1u)
                                           : ((hi >> (k - 32)) & 1u);
                        if (hk && targ[k] == cc) { first = false; break; }
                    }
                    if (first) { val = rowp[cc]; flag = 1; }
                }
                #pragma unroll
                for (int off = 16; off; off >>= 1) {
                    val  += __shfl_xor_sync(0xffffffffu, val, off);
                    flag += __shfl_xor_sync(0xffffffffu, flag, off);
                }
                if ((tid & 31) == 0) { sh_hv[tid >> 5] = val; sh_fl[tid >> 5] = flag; }
            }
            __syncthreads();

            if (tid == 0) {
                float S_all = 0.0f;
                for (int k = 0; k < 8; k++) S_all += sw[k];
                float S_hit = sh_hv[0] + sh_hv[1];
                int   m     = sh_fl[0] + sh_fl[1];

                const float em1 = 0.36787944117144233f;  // e^-1
                float fm = (float)m;
                float Z  = fm + ((float)VV - fm) * em1;
                float ph = 1.0f / Z;
                float pm = em1 / Z;
                float ent = fm * ph * logf(ph) + ((float)VV - fm) * pm * logf(pm);
                g_loss[row] = ent - (pm * S_all + (ph - pm) * S_hit);
            }
            __syncthreads();
        }
    }

    // ---------------- ticket: last block does the final scalar ----------------
    __syncthreads();
    if (tid == 0) {
        __threadfence();                          // release my g_* writes
        unsigned old = atomicAdd(&g_ctr, 1u);
        sh_win = (old == NBLK - 1) ? 1 : 0;
    }
    __syncthreads();

    if (sh_win) {
        __threadfence();                          // acquire everyone's writes
        if (tid < BB) {
            float s = 0.0f;
            for (int i = 0; i < PP; i++) s += g_loss[tid * PP + i];
            pb[tid] = s / ((float)g_len[tid] + 1e-13f);
        }
        __syncthreads();
        if (tid == 0) {
            float acc = 0.0f, n = 0.0f;
            for (int k = 0; k < BB; k++) {
                acc += pb[k];
                if (g_len[k] > 0) n += 1.0f;
            }
            out[0] = acc / (n + 1e-13f);
            // reset state for the next graph replay
            g_ctr = 0;
            g_work = 0;
            for (int k = 0; k < BB; k++) g_dp_done[k] = 0;
        }
    }
}

// ---------------------------------------------------------------------------
extern "C" void kernel_launch(void* const* d_in, const int* in_sizes, int n_in,
                              void* d_out, int out_size) {
    const float* outputs = (const float*)d_in[0];   // (B,P,V) f32 log-probs
    const int*   syms    = (const int*)d_in[1];     // (B,P) i32
    const int*   targets = (const int*)d_in[2];     // (B,L) i32
    const void*  mask    = d_in[3];                 // (B,L) bool-ish

    fused_kernel<<<NBLK, 256>>>(outputs, syms, targets, mask, (float*)d_out);
}